// round 1
// baseline (speedup 1.0000x reference)
#include <cuda_runtime.h>
#include <cstdint>
#include <cstddef>

#define NSEQ 1024
#define DIM  1024
#define BATCH 4
#define HEADS 16
#define DK 64
#define LAYERS 4

// ---------------- scratch buffers (device globals; no allocation) ----------------
__device__ float g_x[BATCH * DIM * NSEQ];        // running x
__device__ float g_q[BATCH * DIM * NSEQ];
__device__ float g_k[BATCH * DIM * NSEQ];
__device__ float g_v[BATCH * DIM * NSEQ];
__device__ float g_a[BATCH * DIM * NSEQ];        // attn output
__device__ float g_m[BATCH * DIM * NSEQ];        // merged
__device__ float g_c[BATCH * 2 * DIM * NSEQ];    // concat
__device__ float g_h[BATCH * 2 * DIM * NSEQ];    // hidden after BN/ReLU
__device__ float g_s[(size_t)BATCH * HEADS * NSEQ * NSEQ]; // scores (256 MB)

// ---------------- generic fp32 GEMM: out[b,o,n] = sum_c W[o,c] X[b,c,n] (+epilogue) ----
// EPI 0: + bias
// EPI 1: relu( (acc+bias)*scale + shift )  (BatchNorm eval fused)
// EPI 2: + bias + res[b,o,n]               (residual)
template<int EPI>
__global__ __launch_bounds__(256) void gemm_k(
    const float* __restrict__ W, const float* __restrict__ X,
    const float* __restrict__ bias, float* __restrict__ out,
    int Cout, int Cin,
    const float* __restrict__ g, const float* __restrict__ bt,
    const float* __restrict__ mu, const float* __restrict__ var,
    const float* __restrict__ res)
{
    __shared__ float Ws[16][128];
    __shared__ float Xs[16][128];

    const int b  = blockIdx.z;
    const int n0 = blockIdx.x * 128;
    const int o0 = blockIdx.y * 128;
    const float* Xb = X + (size_t)b * Cin * NSEQ;

    const int tid = threadIdx.x;
    const int tx = tid & 15;       // n dim
    const int ty = tid >> 4;       // o dim

    float acc[8][8];
    #pragma unroll
    for (int i = 0; i < 8; i++)
        #pragma unroll
        for (int j = 0; j < 8; j++) acc[i][j] = 0.f;

    for (int k0 = 0; k0 < Cin; k0 += 16) {
        // W tile: 128(o) x 16(k), scatter-transpose into Ws[k][o]
        {
            int idx = tid;
            #pragma unroll
            for (int it = 0; it < 2; it++, idx += 256) {
                int o  = idx >> 2;
                int kq = (idx & 3) << 2;
                float4 w4 = *(const float4*)(W + (size_t)(o0 + o) * Cin + k0 + kq);
                Ws[kq + 0][o] = w4.x; Ws[kq + 1][o] = w4.y;
                Ws[kq + 2][o] = w4.z; Ws[kq + 3][o] = w4.w;
            }
        }
        // X tile: 16(k) x 128(n), direct
        {
            int idx = tid;
            #pragma unroll
            for (int it = 0; it < 2; it++, idx += 256) {
                int kk = idx >> 5;
                int nq = (idx & 31) << 2;
                *(float4*)&Xs[kk][nq] =
                    *(const float4*)(Xb + (size_t)(k0 + kk) * NSEQ + n0 + nq);
            }
        }
        __syncthreads();
        #pragma unroll
        for (int kk = 0; kk < 16; kk++) {
            float4 wlo = *(const float4*)&Ws[kk][ty * 4];
            float4 whi = *(const float4*)&Ws[kk][64 + ty * 4];
            float4 xlo = *(const float4*)&Xs[kk][tx * 4];
            float4 xhi = *(const float4*)&Xs[kk][64 + tx * 4];
            float wr[8] = {wlo.x, wlo.y, wlo.z, wlo.w, whi.x, whi.y, whi.z, whi.w};
            float xr[8] = {xlo.x, xlo.y, xlo.z, xlo.w, xhi.x, xhi.y, xhi.z, xhi.w};
            #pragma unroll
            for (int i = 0; i < 8; i++)
                #pragma unroll
                for (int j = 0; j < 8; j++)
                    acc[i][j] = fmaf(wr[i], xr[j], acc[i][j]);
        }
        __syncthreads();
    }

    float* outb = out + (size_t)b * Cout * NSEQ;
    const float* resb = (EPI == 2) ? res + (size_t)b * Cout * NSEQ : nullptr;
    #pragma unroll
    for (int i = 0; i < 8; i++) {
        int o = o0 + ((i < 4) ? (ty * 4 + i) : (64 + ty * 4 + i - 4));
        float bv = bias[o];
        float scale = 1.f, shift = 0.f;
        if (EPI == 1) {
            float s = g[o] * rsqrtf(var[o] + 1e-5f);
            scale = s; shift = bt[o] - mu[o] * s;
        }
        #pragma unroll
        for (int j = 0; j < 8; j++) {
            int n = n0 + ((j < 4) ? (tx * 4 + j) : (64 + tx * 4 + j - 4));
            float v2 = acc[i][j] + bv;
            if (EPI == 1) v2 = fmaxf(fmaf(v2, scale, shift), 0.f);
            if (EPI == 2) v2 += resb[(size_t)o * NSEQ + n];
            outb[(size_t)o * NSEQ + n] = v2;
        }
    }
}

// ---------------- scores: S[bh,n,m] = (1/8) * sum_dk q[b,dk*16+h,n] * k[b,dk*16+h,m] ----
__global__ __launch_bounds__(256) void scores_k(
    const float* __restrict__ q, const float* __restrict__ k, float* __restrict__ S)
{
    const int bh = blockIdx.z;
    const int b = bh >> 4, h = bh & 15;
    const int m0 = blockIdx.x * 128;
    const int n0 = blockIdx.y * 128;
    const float* qb = q + ((size_t)b * DIM + h) * NSEQ;  // + dk*16*NSEQ + n
    const float* kb = k + ((size_t)b * DIM + h) * NSEQ;

    __shared__ float Qs[16][128];
    __shared__ float Ks[16][128];

    const int tid = threadIdx.x;
    const int tx = tid & 15;   // m
    const int ty = tid >> 4;   // n

    float acc[8][8];
    #pragma unroll
    for (int i = 0; i < 8; i++)
        #pragma unroll
        for (int j = 0; j < 8; j++) acc[i][j] = 0.f;

    for (int k0 = 0; k0 < DK; k0 += 16) {
        {
            int idx = tid;
            #pragma unroll
            for (int it = 0; it < 2; it++, idx += 256) {
                int kk = idx >> 5;
                int nq = (idx & 31) << 2;
                *(float4*)&Qs[kk][nq] =
                    *(const float4*)(qb + (size_t)(k0 + kk) * (16 * NSEQ) + n0 + nq);
                *(float4*)&Ks[kk][nq] =
                    *(const float4*)(kb + (size_t)(k0 + kk) * (16 * NSEQ) + m0 + nq);
            }
        }
        __syncthreads();
        #pragma unroll
        for (int kk = 0; kk < 16; kk++) {
            float4 wlo = *(const float4*)&Qs[kk][ty * 4];
            float4 whi = *(const float4*)&Qs[kk][64 + ty * 4];
            float4 xlo = *(const float4*)&Ks[kk][tx * 4];
            float4 xhi = *(const float4*)&Ks[kk][64 + tx * 4];
            float wr[8] = {wlo.x, wlo.y, wlo.z, wlo.w, whi.x, whi.y, whi.z, whi.w};
            float xr[8] = {xlo.x, xlo.y, xlo.z, xlo.w, xhi.x, xhi.y, xhi.z, xhi.w};
            #pragma unroll
            for (int i = 0; i < 8; i++)
                #pragma unroll
                for (int j = 0; j < 8; j++)
                    acc[i][j] = fmaf(wr[i], xr[j], acc[i][j]);
        }
        __syncthreads();
    }

    float* Sb = S + (size_t)bh * NSEQ * NSEQ;
    #pragma unroll
    for (int i = 0; i < 8; i++) {
        int n = n0 + ((i < 4) ? (ty * 4 + i) : (64 + ty * 4 + i - 4));
        #pragma unroll
        for (int j = 0; j < 8; j++) {
            int m = m0 + ((j < 4) ? (tx * 4 + j) : (64 + tx * 4 + j - 4));
            Sb[(size_t)n * NSEQ + m] = acc[i][j] * 0.125f;
        }
    }
}

// ---------------- softmax over last dim (rows of 1024) ----------------
__global__ __launch_bounds__(256) void softmax_k(float* __restrict__ S)
{
    float* row = S + (size_t)blockIdx.x * NSEQ;
    const int t = threadIdx.x;
    float4 v = *(const float4*)(row + t * 4);

    float mx = fmaxf(fmaxf(v.x, v.y), fmaxf(v.z, v.w));
    #pragma unroll
    for (int o = 16; o; o >>= 1) mx = fmaxf(mx, __shfl_xor_sync(0xffffffffu, mx, o));
    __shared__ float smx[8];
    __shared__ float ssm[8];
    if ((t & 31) == 0) smx[t >> 5] = mx;
    __syncthreads();
    float bm = smx[0];
    #pragma unroll
    for (int i = 1; i < 8; i++) bm = fmaxf(bm, smx[i]);

    v.x = __expf(v.x - bm); v.y = __expf(v.y - bm);
    v.z = __expf(v.z - bm); v.w = __expf(v.w - bm);
    float s = v.x + v.y + v.z + v.w;
    #pragma unroll
    for (int o = 16; o; o >>= 1) s += __shfl_xor_sync(0xffffffffu, s, o);
    if ((t & 31) == 0) ssm[t >> 5] = s;
    __syncthreads();
    float bs = 0.f;
    #pragma unroll
    for (int i = 0; i < 8; i++) bs += ssm[i];
    float inv = 1.0f / bs;
    v.x *= inv; v.y *= inv; v.z *= inv; v.w *= inv;
    *(float4*)(row + t * 4) = v;
}

// ---------------- attn: A[b,dk*16+h,n] = sum_m W[bh,n,m] v[b,dk*16+h,m] ----------------
__global__ __launch_bounds__(256) void attnv_k(
    const float* __restrict__ S, const float* __restrict__ v, float* __restrict__ A)
{
    const int bh = blockIdx.y;
    const int b = bh >> 4, h = bh & 15;
    const int n0 = blockIdx.x * 128;
    const float* vb = v + ((size_t)b * DIM + h) * NSEQ;
    const float* Sb = S + (size_t)bh * NSEQ * NSEQ;

    __shared__ float Vs[16][64];
    __shared__ float Ws2[16][128];

    const int tid = threadIdx.x;
    const int tx = tid & 15;   // n
    const int ty = tid >> 4;   // dk (4 per thread)

    float acc[4][8];
    #pragma unroll
    for (int i = 0; i < 4; i++)
        #pragma unroll
        for (int j = 0; j < 8; j++) acc[i][j] = 0.f;

    for (int m0 = 0; m0 < NSEQ; m0 += 16) {
        {
            int dk = tid >> 2;
            int kq = (tid & 3) << 2;
            float4 v4 = *(const float4*)(vb + (size_t)dk * (16 * NSEQ) + m0 + kq);
            Vs[kq + 0][dk] = v4.x; Vs[kq + 1][dk] = v4.y;
            Vs[kq + 2][dk] = v4.z; Vs[kq + 3][dk] = v4.w;
        }
        {
            int idx = tid;
            #pragma unroll
            for (int it = 0; it < 2; it++, idx += 256) {
                int n  = idx >> 2;
                int kq = (idx & 3) << 2;
                float4 w4 = *(const float4*)(Sb + (size_t)(n0 + n) * NSEQ + m0 + kq);
                Ws2[kq + 0][n] = w4.x; Ws2[kq + 1][n] = w4.y;
                Ws2[kq + 2][n] = w4.z; Ws2[kq + 3][n] = w4.w;
            }
        }
        __syncthreads();
        #pragma unroll
        for (int kk = 0; kk < 16; kk++) {
            float4 vv  = *(const float4*)&Vs[kk][ty * 4];
            float4 xlo = *(const float4*)&Ws2[kk][tx * 4];
            float4 xhi = *(const float4*)&Ws2[kk][64 + tx * 4];
            float vr[4] = {vv.x, vv.y, vv.z, vv.w};
            float xr[8] = {xlo.x, xlo.y, xlo.z, xlo.w, xhi.x, xhi.y, xhi.z, xhi.w};
            #pragma unroll
            for (int i = 0; i < 4; i++)
                #pragma unroll
                for (int j = 0; j < 8; j++)
                    acc[i][j] = fmaf(vr[i], xr[j], acc[i][j]);
        }
        __syncthreads();
    }

    float* ab = A + ((size_t)b * DIM + h) * NSEQ;
    #pragma unroll
    for (int i = 0; i < 4; i++) {
        int dk = ty * 4 + i;
        #pragma unroll
        for (int j = 0; j < 8; j++) {
            int n = n0 + ((j < 4) ? (tx * 4 + j) : (64 + tx * 4 + j - 4));
            ab[(size_t)dk * (16 * NSEQ) + n] = acc[i][j];
        }
    }
}

// ---------------- concat(merged, x) -> (B, 2D, N) ----------------
__global__ __launch_bounds__(256) void concat_k(
    const float* __restrict__ m, const float* __restrict__ x, float* __restrict__ o)
{
    size_t i = ((size_t)blockIdx.x * 256 + threadIdx.x) * 4;   // over 8M floats
    const size_t per_b = (size_t)2 * DIM * NSEQ;               // 2M floats
    size_t b = i / per_b;
    size_t r = i % per_b;
    const size_t half = (size_t)DIM * NSEQ;
    const float* src = (r < half) ? (m + b * half + r) : (x + b * half + (r - half));
    *(float4*)(o + i) = *(const float4*)src;
}

// ---------------- host launcher ----------------
extern "C" void kernel_launch(void* const* d_in, const int* in_sizes, int n_in,
                              void* d_out, int out_size)
{
    const float* motion = (const float*)d_in[0];
    const float* Wq  = (const float*)d_in[1];
    const float* bq  = (const float*)d_in[2];
    const float* Wk  = (const float*)d_in[3];
    const float* bk  = (const float*)d_in[4];
    const float* Wv  = (const float*)d_in[5];
    const float* bv  = (const float*)d_in[6];
    const float* Wm  = (const float*)d_in[7];
    const float* bm  = (const float*)d_in[8];
    const float* Wp1 = (const float*)d_in[9];
    const float* bp1 = (const float*)d_in[10];
    const float* bng = (const float*)d_in[11];
    const float* bnb = (const float*)d_in[12];
    const float* bnm = (const float*)d_in[13];
    const float* bnv = (const float*)d_in[14];
    const float* Wp2 = (const float*)d_in[15];
    const float* bp2 = (const float*)d_in[16];

    float *xb, *qb, *kb, *vb2, *ab, *mb, *cb, *hb, *sb;
    cudaGetSymbolAddress((void**)&xb, g_x);
    cudaGetSymbolAddress((void**)&qb, g_q);
    cudaGetSymbolAddress((void**)&kb, g_k);
    cudaGetSymbolAddress((void**)&vb2, g_v);
    cudaGetSymbolAddress((void**)&ab, g_a);
    cudaGetSymbolAddress((void**)&mb, g_m);
    cudaGetSymbolAddress((void**)&cb, g_c);
    cudaGetSymbolAddress((void**)&hb, g_h);
    cudaGetSymbolAddress((void**)&sb, g_s);

    cudaMemcpyAsync(xb, motion, (size_t)BATCH * DIM * NSEQ * sizeof(float),
                    cudaMemcpyDeviceToDevice);

    const size_t DD  = (size_t)DIM * DIM;         // 1M
    const size_t DD2 = (size_t)2 * DIM * 2 * DIM; // 4M (Wp1 per-layer)
    const size_t DD3 = (size_t)DIM * 2 * DIM;     // 2M (Wp2 per-layer)

    dim3 gGemmD(8, 8, BATCH);     // Cout=1024
    dim3 gGemm2D(8, 16, BATCH);   // Cout=2048
    dim3 gScores(8, 8, BATCH * HEADS);
    dim3 gAttn(8, BATCH * HEADS);

    for (int l = 0; l < LAYERS; l++) {
        gemm_k<0><<<gGemmD, 256>>>(Wq + l * DD, xb, bq + l * DIM, qb, DIM, DIM,
                                   nullptr, nullptr, nullptr, nullptr, nullptr);
        gemm_k<0><<<gGemmD, 256>>>(Wk + l * DD, xb, bk + l * DIM, kb, DIM, DIM,
                                   nullptr, nullptr, nullptr, nullptr, nullptr);
        gemm_k<0><<<gGemmD, 256>>>(Wv + l * DD, xb, bv + l * DIM, vb2, DIM, DIM,
                                   nullptr, nullptr, nullptr, nullptr, nullptr);
        scores_k<<<gScores, 256>>>(qb, kb, sb);
        softmax_k<<<BATCH * HEADS * NSEQ, 256>>>(sb);
        attnv_k<<<gAttn, 256>>>(sb, vb2, ab);
        gemm_k<0><<<gGemmD, 256>>>(Wm + l * DD, ab, bm + l * DIM, mb, DIM, DIM,
                                   nullptr, nullptr, nullptr, nullptr, nullptr);
        concat_k<<<(BATCH * 2 * DIM * NSEQ) / (256 * 4), 256>>>(mb, xb, cb);
        gemm_k<1><<<gGemm2D, 256>>>(Wp1 + l * DD2, cb, bp1 + l * 2 * DIM, hb,
                                    2 * DIM, 2 * DIM,
                                    bng + l * 2 * DIM, bnb + l * 2 * DIM,
                                    bnm + l * 2 * DIM, bnv + l * 2 * DIM, nullptr);
        float* dst = (l == LAYERS - 1) ? (float*)d_out : xb;
        gemm_k<2><<<gGemmD, 256>>>(Wp2 + l * DD3, hb, bp2 + l * DIM, dst,
                                   DIM, 2 * DIM,
                                   nullptr, nullptr, nullptr, nullptr, xb);
    }
}

// round 7
// speedup vs baseline: 1.5994x; 1.5994x over previous
#include <cuda_runtime.h>
#include <cuda_bf16.h>
#include <cstdint>
#include <cstddef>

#define NSEQ 1024
#define DIM  1024
#define BATCH 4
#define HEADS 16
#define DK 64
#define LAYERS 4

// ---------------- fp32 scratch (device globals; no allocation) ----------------
__device__ float g_x[BATCH * DIM * NSEQ];        // running x  (c,n)
__device__ float g_q[BATCH * DIM * NSEQ];
__device__ float g_k[BATCH * DIM * NSEQ];
__device__ float g_v[BATCH * DIM * NSEQ];
__device__ float g_a[BATCH * DIM * NSEQ];        // attn output (c,n)
__device__ float g_m[BATCH * DIM * NSEQ];        // merged (c,n)
__device__ float g_h[BATCH * 2 * DIM * NSEQ];    // hidden after BN/ReLU (c,n)
__device__ float g_s[(size_t)BATCH * HEADS * NSEQ * NSEQ]; // scores (256 MB)

// ---------------- bf16 hi/lo split buffers ----------------
// weights (split once per launch)
__device__ __align__(256) __nv_bfloat16 g_Wqh[LAYERS * DIM * DIM];
__device__ __align__(256) __nv_bfloat16 g_Wql[LAYERS * DIM * DIM];
__device__ __align__(256) __nv_bfloat16 g_Wkh[LAYERS * DIM * DIM];
__device__ __align__(256) __nv_bfloat16 g_Wkl[LAYERS * DIM * DIM];
__device__ __align__(256) __nv_bfloat16 g_Wvh[LAYERS * DIM * DIM];
__device__ __align__(256) __nv_bfloat16 g_Wvl[LAYERS * DIM * DIM];
__device__ __align__(256) __nv_bfloat16 g_Wmh[LAYERS * DIM * DIM];
__device__ __align__(256) __nv_bfloat16 g_Wml[LAYERS * DIM * DIM];
__device__ __align__(256) __nv_bfloat16 g_Wp1h[LAYERS * 2 * DIM * 2 * DIM];
__device__ __align__(256) __nv_bfloat16 g_Wp1l[LAYERS * 2 * DIM * 2 * DIM];
__device__ __align__(256) __nv_bfloat16 g_Wp2h[LAYERS * DIM * 2 * DIM];
__device__ __align__(256) __nv_bfloat16 g_Wp2l[LAYERS * DIM * 2 * DIM];
// activations, transposed to (b, n, C) layout, split hi/lo
__device__ __align__(256) __nv_bfloat16 g_xTh[BATCH * NSEQ * DIM];
__device__ __align__(256) __nv_bfloat16 g_xTl[BATCH * NSEQ * DIM];
__device__ __align__(256) __nv_bfloat16 g_aTh[BATCH * NSEQ * DIM];
__device__ __align__(256) __nv_bfloat16 g_aTl[BATCH * NSEQ * DIM];
__device__ __align__(256) __nv_bfloat16 g_cTh[BATCH * NSEQ * 2 * DIM];
__device__ __align__(256) __nv_bfloat16 g_cTl[BATCH * NSEQ * 2 * DIM];
__device__ __align__(256) __nv_bfloat16 g_hTh[BATCH * NSEQ * 2 * DIM];
__device__ __align__(256) __nv_bfloat16 g_hTl[BATCH * NSEQ * 2 * DIM];

// ======================= PTX helpers (all valid compute_103 PTX) =======================
__device__ __forceinline__ uint32_t smem_u32(const void* p) {
    uint32_t a;
    asm("{ .reg .u64 t; cvta.to.shared.u64 t, %1; cvt.u32.u64 %0, t; }" : "=r"(a) : "l"(p));
    return a;
}
#define CP_ASYNC16(dst, src) \
    asm volatile("cp.async.cg.shared.global [%0], [%1], 16;" :: "r"(dst), "l"(src) : "memory")
#define CP_COMMIT()   asm volatile("cp.async.commit_group;" ::: "memory")
#define CP_WAIT(N)    asm volatile("cp.async.wait_group %0;" :: "n"(N) : "memory")
#define LDM4(r, addr) \
    asm volatile("ldmatrix.sync.aligned.m8n8.x4.shared.b16 {%0,%1,%2,%3}, [%4];" \
        : "=r"((r)[0]), "=r"((r)[1]), "=r"((r)[2]), "=r"((r)[3]) : "r"(addr))
#define MMA_BF16(d, a, b0, b1) \
    asm volatile("mma.sync.aligned.m16n8k16.row.col.f32.bf16.bf16.f32 " \
        "{%0,%1,%2,%3}, {%4,%5,%6,%7}, {%8,%9}, {%0,%1,%2,%3};" \
        : "+f"((d)[0]), "+f"((d)[1]), "+f"((d)[2]), "+f"((d)[3]) \
        : "r"((a)[0]), "r"((a)[1]), "r"((a)[2]), "r"((a)[3]), "r"(b0), "r"(b1))

// ======================= tensor GEMM (3x bf16 split, mma.sync) =======================
// out[b, o, n] = sum_c W[o,c] * X[b,n,c]  with W,X given as bf16 hi/lo pairs.
// CTA tile 128(o) x 128(n); 8 warps as 2(M) x 4(N); warp tile 64 x 32.
// K chunks of 32; double-buffered cp.async.
#define SROW   40                      // bf16 elems per smem row (32 used + 8 pad)
#define MATB   (128 * SROW * 2)        // 10240 B per matrix
#define STAGEB (4 * MATB)              // Ah, Al, Bh, Bl
#define GSMEM  (2 * STAGEB)            // 81920 B

template<int EPI>
__global__ __launch_bounds__(256) void gemmt_k(
    const __nv_bfloat16* __restrict__ Wh, const __nv_bfloat16* __restrict__ Wl,
    const __nv_bfloat16* __restrict__ Xh, const __nv_bfloat16* __restrict__ Xl,
    const float* __restrict__ bias, float* __restrict__ out,
    int Cout, int Cin,
    const float* __restrict__ g, const float* __restrict__ bt,
    const float* __restrict__ mu, const float* __restrict__ var,
    const float* __restrict__ res)
{
    extern __shared__ __align__(16) char sm[];
    const int tid = threadIdx.x;
    const int l = tid & 31, wid = tid >> 5;
    const int wm = wid & 1, wn = wid >> 1;
    const int b = blockIdx.z, n0 = blockIdx.x * 128, o0 = blockIdx.y * 128;

    const __nv_bfloat16* WhB = Wh + (size_t)o0 * Cin;
    const __nv_bfloat16* WlB = Wl + (size_t)o0 * Cin;
    const __nv_bfloat16* XhB = Xh + ((size_t)b * NSEQ + n0) * Cin;
    const __nv_bfloat16* XlB = Xl + ((size_t)b * NSEQ + n0) * Cin;

    const uint32_t sbase = smem_u32(sm);
    const int NC = Cin >> 5;

    // per-lane ldmatrix offsets (bytes within a matrix)
    const int rowA = l & 15;                    // (l&7) + 8*bit3
    const int colA = (l >> 4) << 3;
    int aoff[4];
    #pragma unroll
    for (int mt = 0; mt < 4; mt++)
        aoff[mt] = ((wm * 64 + mt * 16 + rowA) * SROW + colA) * 2;
    int boff[2];
    #pragma unroll
    for (int ntp = 0; ntp < 2; ntp++)
        boff[ntp] = ((wn * 32 + ntp * 16 + ((l >> 4) & 1) * 8 + (l & 7)) * SROW
                     + ((l >> 3) & 1) * 8) * 2;

    float acc[4][4][4];
    #pragma unroll
    for (int i = 0; i < 4; i++)
        #pragma unroll
        for (int j = 0; j < 4; j++)
            #pragma unroll
            for (int q = 0; q < 4; q++) acc[i][j][q] = 0.f;

    // chunk loader: 512 x 16B per matrix-set
    auto load = [&](int kc) {
        char* base = sm + (kc & 1) * STAGEB;
        const __nv_bfloat16* srcs[4] = {WhB, WlB, XhB, XlB};
        #pragma unroll
        for (int i = 0; i < 2; i++) {
            int s = tid * 2 + i;           // 0..511
            int row = s >> 2, seg = s & 3;
            #pragma unroll
            for (int m4 = 0; m4 < 4; m4++) {
                uint32_t dst = smem_u32(base + m4 * MATB + row * (SROW * 2) + seg * 16);
                const __nv_bfloat16* src = srcs[m4] + (size_t)row * Cin + kc * 32 + seg * 8;
                CP_ASYNC16(dst, src);
            }
        }
        CP_COMMIT();
    };

    load(0);
    for (int kc = 0; kc < NC; kc++) {
        if (kc + 1 < NC) { load(kc + 1); CP_WAIT(1); }
        else            { CP_WAIT(0); }
        __syncthreads();

        const uint32_t S = sbase + (kc & 1) * STAGEB;
        #pragma unroll
        for (int ks = 0; ks < 2; ks++) {
            unsigned fa[4][4], fbh[2][4], fbl[2][4];
            #pragma unroll
            for (int mt = 0; mt < 4; mt++) LDM4(fa[mt], S + aoff[mt] + ks * 32);
            #pragma unroll
            for (int p = 0; p < 2; p++) {
                LDM4(fbh[p], S + 2 * MATB + boff[p] + ks * 32);
                LDM4(fbl[p], S + 3 * MATB + boff[p] + ks * 32);
            }
            // hi*hi  and  hi*lo
            #pragma unroll
            for (int mt = 0; mt < 4; mt++)
                #pragma unroll
                for (int nt = 0; nt < 4; nt++) {
                    MMA_BF16(acc[mt][nt], fa[mt], fbh[nt >> 1][(nt & 1) * 2],
                             fbh[nt >> 1][(nt & 1) * 2 + 1]);
                    MMA_BF16(acc[mt][nt], fa[mt], fbl[nt >> 1][(nt & 1) * 2],
                             fbl[nt >> 1][(nt & 1) * 2 + 1]);
                }
            // lo*hi
            #pragma unroll
            for (int mt = 0; mt < 4; mt++) LDM4(fa[mt], S + MATB + aoff[mt] + ks * 32);
            #pragma unroll
            for (int mt = 0; mt < 4; mt++)
                #pragma unroll
                for (int nt = 0; nt < 4; nt++)
                    MMA_BF16(acc[mt][nt], fa[mt], fbh[nt >> 1][(nt & 1) * 2],
                             fbh[nt >> 1][(nt & 1) * 2 + 1]);
        }
        __syncthreads();
    }

    // ---------------- epilogue ----------------
    #pragma unroll
    for (int mt = 0; mt < 4; mt++) {
        int o1 = o0 + wm * 64 + mt * 16 + (l >> 2);
        int o2 = o1 + 8;
        float b1v = bias[o1], b2v = bias[o2];
        float sc1 = 1.f, sh1 = 0.f, sc2 = 1.f, sh2 = 0.f;
        if (EPI == 1) {
            float s1 = g[o1] * rsqrtf(var[o1] + 1e-5f);
            sc1 = s1; sh1 = bt[o1] - mu[o1] * s1;
            float s2 = g[o2] * rsqrtf(var[o2] + 1e-5f);
            sc2 = s2; sh2 = bt[o2] - mu[o2] * s2;
        }
        float* r1 = out + ((size_t)b * Cout + o1) * NSEQ + n0 + wn * 32;
        float* r2 = out + ((size_t)b * Cout + o2) * NSEQ + n0 + wn * 32;
        const float* q1 = (EPI == 2) ? res + ((size_t)b * Cout + o1) * NSEQ + n0 + wn * 32 : nullptr;
        const float* q2 = (EPI == 2) ? res + ((size_t)b * Cout + o2) * NSEQ + n0 + wn * 32 : nullptr;
        #pragma unroll
        for (int nt = 0; nt < 4; nt++) {
            int nn = nt * 8 + (l & 3) * 2;
            float v0 = acc[mt][nt][0] + b1v, v1 = acc[mt][nt][1] + b1v;
            float v2 = acc[mt][nt][2] + b2v, v3 = acc[mt][nt][3] + b2v;
            if (EPI == 1) {
                v0 = fmaxf(fmaf(v0, sc1, sh1), 0.f); v1 = fmaxf(fmaf(v1, sc1, sh1), 0.f);
                v2 = fmaxf(fmaf(v2, sc2, sh2), 0.f); v3 = fmaxf(fmaf(v3, sc2, sh2), 0.f);
            }
            if (EPI == 2) {
                float2 ra = *(const float2*)(q1 + nn);
                float2 rb = *(const float2*)(q2 + nn);
                v0 += ra.x; v1 += ra.y; v2 += rb.x; v3 += rb.y;
            }
            *(float2*)(r1 + nn) = make_float2(v0, v1);
            *(float2*)(r2 + nn) = make_float2(v2, v3);
        }
    }
}

// ======================= fp32 -> bf16 hi/lo split (weights) =======================
__global__ __launch_bounds__(256) void split_k(
    const float* __restrict__ src, __nv_bfloat16* __restrict__ hi,
    __nv_bfloat16* __restrict__ lo, int n4)
{
    int i = blockIdx.x * 256 + threadIdx.x;
    if (i >= n4) return;
    float4 v = ((const float4*)src)[i];
    __nv_bfloat16 hx = __float2bfloat16(v.x), hy = __float2bfloat16(v.y);
    __nv_bfloat16 hz = __float2bfloat16(v.z), hw = __float2bfloat16(v.w);
    __nv_bfloat16 lx = __float2bfloat16(v.x - __bfloat162float(hx));
    __nv_bfloat16 ly = __float2bfloat16(v.y - __bfloat162float(hy));
    __nv_bfloat16 lz = __float2bfloat16(v.z - __bfloat162float(hz));
    __nv_bfloat16 lw = __float2bfloat16(v.w - __bfloat162float(hw));
    uint2 H, L2;
    H.x = (uint32_t)__bfloat16_as_ushort(hx) | ((uint32_t)__bfloat16_as_ushort(hy) << 16);
    H.y = (uint32_t)__bfloat16_as_ushort(hz) | ((uint32_t)__bfloat16_as_ushort(hw) << 16);
    L2.x = (uint32_t)__bfloat16_as_ushort(lx) | ((uint32_t)__bfloat16_as_ushort(ly) << 16);
    L2.y = (uint32_t)__bfloat16_as_ushort(lz) | ((uint32_t)__bfloat16_as_ushort(lw) << 16);
    ((uint2*)hi)[i] = H;
    ((uint2*)lo)[i] = L2;
}

// ======================= transpose + split: (b,c,n) fp32 -> (b,n,C) bf16 hi/lo ====
__global__ __launch_bounds__(256) void transposeS_k(
    const float* __restrict__ src, __nv_bfloat16* __restrict__ dstH,
    __nv_bfloat16* __restrict__ dstL, int C, int dstStride, int dstOff)
{
    __shared__ float t[32][33];
    const int b  = blockIdx.z;
    const int n0 = blockIdx.x * 32;
    const int c0 = blockIdx.y * 32;
    const float* s = src + (size_t)b * C * NSEQ;
    const size_t dbase = (size_t)b * NSEQ * dstStride + dstOff;
    const int tx = threadIdx.x & 31, ty = threadIdx.x >> 5;
    #pragma unroll
    for (int i = 0; i < 32; i += 8)
        t[ty + i][tx] = s[(size_t)(c0 + ty + i) * NSEQ + n0 + tx];
    __syncthreads();
    #pragma unroll
    for (int i = 0; i < 32; i += 8) {
        float v = t[tx][ty + i];
        __nv_bfloat16 h = __float2bfloat16(v);
        __nv_bfloat16 lo = __float2bfloat16(v - __bfloat162float(h));
        size_t idx = dbase + (size_t)(n0 + ty + i) * dstStride + c0 + tx;
        dstH[idx] = h;
        dstL[idx] = lo;
    }
}

// ======================= attention (SIMT fp32, proven in R1) =======================
__global__ __launch_bounds__(256) void scores_k(
    const float* __restrict__ q, const float* __restrict__ k, float* __restrict__ S)
{
    const int bh = blockIdx.z;
    const int b = bh >> 4, h = bh & 15;
    const int m0 = blockIdx.x * 128;
    const int n0 = blockIdx.y * 128;
    const float* qb = q + ((size_t)b * DIM + h) * NSEQ;
    const float* kb = k + ((size_t)b * DIM + h) * NSEQ;

    __shared__ float Qs[16][128];
    __shared__ float Ks[16][128];

    const int tid = threadIdx.x;
    const int tx = tid & 15;
    const int ty = tid >> 4;

    float acc[8][8];
    #pragma unroll
    for (int i = 0; i < 8; i++)
        #pragma unroll
        for (int j = 0; j < 8; j++) acc[i][j] = 0.f;

    for (int k0 = 0; k0 < DK; k0 += 16) {
        {
            int idx = tid;
            #pragma unroll
            for (int it = 0; it < 2; it++, idx += 256) {
                int kk = idx >> 5;
                int nq = (idx & 31) << 2;
                *(float4*)&Qs[kk][nq] =
                    *(const float4*)(qb + (size_t)(k0 + kk) * (16 * NSEQ) + n0 + nq);
                *(float4*)&Ks[kk][nq] =
                    *(const float4*)(kb + (size_t)(k0 + kk) * (16 * NSEQ) + m0 + nq);
            }
        }
        __syncthreads();
        #pragma unroll
        for (int kk = 0; kk < 16; kk++) {
            float4 wlo = *(const float4*)&Qs[kk][ty * 4];
            float4 whi = *(const float4*)&Qs[kk][64 + ty * 4];
            float4 xlo = *(const float4*)&Ks[kk][tx * 4];
            float4 xhi = *(const float4*)&Ks[kk][64 + tx * 4];
            float wr[8] = {wlo.x, wlo.y, wlo.z, wlo.w, whi.x, whi.y, whi.z, whi.w};
            float xr[8] = {xlo.x, xlo.y, xlo.z, xlo.w, xhi.x, xhi.y, xhi.z, xhi.w};
            #pragma unroll
            for (int i = 0; i < 8; i++)
                #pragma unroll
                for (int j = 0; j < 8; j++)
                    acc[i][j] = fmaf(wr[i], xr[j], acc[i][j]);
        }
        __syncthreads();
    }

    float* Sb = S + (size_t)bh * NSEQ * NSEQ;
    #pragma unroll
    for (int i = 0; i < 8; i++) {
        int n = n0 + ((i < 4) ? (ty * 4 + i) : (64 + ty * 4 + i - 4));
        #pragma unroll
        for (int j = 0; j < 8; j++) {
            int m = m0 + ((j < 4) ? (tx * 4 + j) : (64 + tx * 4 + j - 4));
            Sb[(size_t)n * NSEQ + m] = acc[i][j] * 0.125f;
        }
    }
}

__global__ __launch_bounds__(256) void softmax_k(float* __restrict__ S)
{
    float* row = S + (size_t)blockIdx.x * NSEQ;
    const int t = threadIdx.x;
    float4 v = *(const float4*)(row + t * 4);

    float mx = fmaxf(fmaxf(v.x, v.y), fmaxf(v.z, v.w));
    #pragma unroll
    for (int o = 16; o; o >>= 1) mx = fmaxf(mx, __shfl_xor_sync(0xffffffffu, mx, o));
    __shared__ float smx[8];
    __shared__ float ssm[8];
    if ((t & 31) == 0) smx[t >> 5] = mx;
    __syncthreads();
    float bm = smx[0];
    #pragma unroll
    for (int i = 1; i < 8; i++) bm = fmaxf(bm, smx[i]);

    v.x = __expf(v.x - bm); v.y = __expf(v.y - bm);
    v.z = __expf(v.z - bm); v.w = __expf(v.w - bm);
    float s = v.x + v.y + v.z + v.w;
    #pragma unroll
    for (int o = 16; o; o >>= 1) s += __shfl_xor_sync(0xffffffffu, s, o);
    if ((t & 31) == 0) ssm[t >> 5] = s;
    __syncthreads();
    float bs = 0.f;
    #pragma unroll
    for (int i = 0; i < 8; i++) bs += ssm[i];
    float inv = 1.0f / bs;
    v.x *= inv; v.y *= inv; v.z *= inv; v.w *= inv;
    *(float4*)(row + t * 4) = v;
}

__global__ __launch_bounds__(256) void attnv_k(
    const float* __restrict__ S, const float* __restrict__ v, float* __restrict__ A)
{
    const int bh = blockIdx.y;
    const int b = bh >> 4, h = bh & 15;
    const int n0 = blockIdx.x * 128;
    const float* vb = v + ((size_t)b * DIM + h) * NSEQ;
    const float* Sb = S + (size_t)bh * NSEQ * NSEQ;

    __shared__ float Vs[16][64];
    __shared__ float Ws2[16][128];

    const int tid = threadIdx.x;
    const int tx = tid & 15;
    const int ty = tid >> 4;

    float acc[4][8];
    #pragma unroll
    for (int i = 0; i < 4; i++)
        #pragma unroll
        for (int j = 0; j < 8; j++) acc[i][j] = 0.f;

    for (int m0 = 0; m0 < NSEQ; m0 += 16) {
        {
            int dk = tid >> 2;
            int kq = (tid & 3) << 2;
            float4 v4 = *(const float4*)(vb + (size_t)dk * (16 * NSEQ) + m0 + kq);
            Vs[kq + 0][dk] = v4.x; Vs[kq + 1][dk] = v4.y;
            Vs[kq + 2][dk] = v4.z; Vs[kq + 3][dk] = v4.w;
        }
        {
            int idx = tid;
            #pragma unroll
            for (int it = 0; it < 2; it++, idx += 256) {
                int n  = idx >> 2;
                int kq = (idx & 3) << 2;
                float4 w4 = *(const float4*)(Sb + (size_t)(n0 + n) * NSEQ + m0 + kq);
                Ws2[kq + 0][n] = w4.x; Ws2[kq + 1][n] = w4.y;
                Ws2[kq + 2][n] = w4.z; Ws2[kq + 3][n] = w4.w;
            }
        }
        __syncthreads();
        #pragma unroll
        for (int kk = 0; kk < 16; kk++) {
            float4 vv  = *(const float4*)&Vs[kk][ty * 4];
            float4 xlo = *(const float4*)&Ws2[kk][tx * 4];
            float4 xhi = *(const float4*)&Ws2[kk][64 + tx * 4];
            float vr[4] = {vv.x, vv.y, vv.z, vv.w};
            float xr[8] = {xlo.x, xlo.y, xlo.z, xlo.w, xhi.x, xhi.y, xhi.z, xhi.w};
            #pragma unroll
            for (int i = 0; i < 4; i++)
                #pragma unroll
                for (int j = 0; j < 8; j++)
                    acc[i][j] = fmaf(vr[i], xr[j], acc[i][j]);
        }
        __syncthreads();
    }

    float* ab = A + ((size_t)b * DIM + h) * NSEQ;
    #pragma unroll
    for (int i = 0; i < 4; i++) {
        int dk = ty * 4 + i;
        #pragma unroll
        for (int j = 0; j < 8; j++) {
            int n = n0 + ((j < 4) ? (tx * 4 + j) : (64 + tx * 4 + j - 4));
            ab[(size_t)dk * (16 * NSEQ) + n] = acc[i][j];
        }
    }
}

// ======================= host launcher =======================
extern "C" void kernel_launch(void* const* d_in, const int* in_sizes, int n_in,
                              void* d_out, int out_size)
{
    const float* motion = (const float*)d_in[0];
    const float* Wq  = (const float*)d_in[1];
    const float* bq  = (const float*)d_in[2];
    const float* Wk  = (const float*)d_in[3];
    const float* bk  = (const float*)d_in[4];
    const float* Wv  = (const float*)d_in[5];
    const float* bv  = (const float*)d_in[6];
    const float* Wm  = (const float*)d_in[7];
    const float* bm  = (const float*)d_in[8];
    const float* Wp1 = (const float*)d_in[9];
    const float* bp1 = (const float*)d_in[10];
    const float* bng = (const float*)d_in[11];
    const float* bnb = (const float*)d_in[12];
    const float* bnm = (const float*)d_in[13];
    const float* bnv = (const float*)d_in[14];
    const float* Wp2 = (const float*)d_in[15];
    const float* bp2 = (const float*)d_in[16];

    float *xb, *qb, *kb, *vb2, *ab, *mb, *hb, *sb;
    cudaGetSymbolAddress((void**)&xb, g_x);
    cudaGetSymbolAddress((void**)&qb, g_q);
    cudaGetSymbolAddress((void**)&kb, g_k);
    cudaGetSymbolAddress((void**)&vb2, g_v);
    cudaGetSymbolAddress((void**)&ab, g_a);
    cudaGetSymbolAddress((void**)&mb, g_m);
    cudaGetSymbolAddress((void**)&hb, g_h);
    cudaGetSymbolAddress((void**)&sb, g_s);

    __nv_bfloat16 *Wqh, *Wql, *Wkh, *Wkl, *Wvh, *Wvl, *Wmh, *Wml;
    __nv_bfloat16 *Wp1h, *Wp1l, *Wp2h, *Wp2l;
    __nv_bfloat16 *xTh, *xTl, *aTh, *aTl, *cTh, *cTl, *hTh, *hTl;
    cudaGetSymbolAddress((void**)&Wqh, g_Wqh);  cudaGetSymbolAddress((void**)&Wql, g_Wql);
    cudaGetSymbolAddress((void**)&Wkh, g_Wkh);  cudaGetSymbolAddress((void**)&Wkl, g_Wkl);
    cudaGetSymbolAddress((void**)&Wvh, g_Wvh);  cudaGetSymbolAddress((void**)&Wvl, g_Wvl);
    cudaGetSymbolAddress((void**)&Wmh, g_Wmh);  cudaGetSymbolAddress((void**)&Wml, g_Wml);
    cudaGetSymbolAddress((void**)&Wp1h, g_Wp1h); cudaGetSymbolAddress((void**)&Wp1l, g_Wp1l);
    cudaGetSymbolAddress((void**)&Wp2h, g_Wp2h); cudaGetSymbolAddress((void**)&Wp2l, g_Wp2l);
    cudaGetSymbolAddress((void**)&xTh, g_xTh);  cudaGetSymbolAddress((void**)&xTl, g_xTl);
    cudaGetSymbolAddress((void**)&aTh, g_aTh);  cudaGetSymbolAddress((void**)&aTl, g_aTl);
    cudaGetSymbolAddress((void**)&cTh, g_cTh);  cudaGetSymbolAddress((void**)&cTl, g_cTl);
    cudaGetSymbolAddress((void**)&hTh, g_hTh);  cudaGetSymbolAddress((void**)&hTl, g_hTl);

    cudaFuncSetAttribute(gemmt_k<0>, cudaFuncAttributeMaxDynamicSharedMemorySize, GSMEM);
    cudaFuncSetAttribute(gemmt_k<1>, cudaFuncAttributeMaxDynamicSharedMemorySize, GSMEM);
    cudaFuncSetAttribute(gemmt_k<2>, cudaFuncAttributeMaxDynamicSharedMemorySize, GSMEM);

    cudaMemcpyAsync(xb, motion, (size_t)BATCH * DIM * NSEQ * sizeof(float),
                    cudaMemcpyDeviceToDevice);

    // ---- split all weights once (per launch) ----
    const int nQKVM = LAYERS * DIM * DIM;            // 4M
    const int nP1   = LAYERS * 2 * DIM * 2 * DIM;    // 16M
    const int nP2   = LAYERS * DIM * 2 * DIM;        // 8M
    split_k<<<(nQKVM / 4 + 255) / 256, 256>>>(Wq,  Wqh,  Wql,  nQKVM / 4);
    split_k<<<(nQKVM / 4 + 255) / 256, 256>>>(Wk,  Wkh,  Wkl,  nQKVM / 4);
    split_k<<<(nQKVM / 4 + 255) / 256, 256>>>(Wv,  Wvh,  Wvl,  nQKVM / 4);
    split_k<<<(nQKVM / 4 + 255) / 256, 256>>>(Wm,  Wmh,  Wml,  nQKVM / 4);
    split_k<<<(nP1   / 4 + 255) / 256, 256>>>(Wp1, Wp1h, Wp1l, nP1 / 4);
    split_k<<<(nP2   / 4 + 255) / 256, 256>>>(Wp2, Wp2h, Wp2l, nP2 / 4);

    const size_t DD  = (size_t)DIM * DIM;
    const size_t DD2 = (size_t)2 * DIM * 2 * DIM;
    const size_t DD3 = (size_t)DIM * 2 * DIM;

    dim3 gT1(NSEQ / 32, DIM / 32, BATCH);
    dim3 gT2(NSEQ / 32, 2 * DIM / 32, BATCH);
    dim3 gGemmD(8, 8, BATCH);     // Cout=1024
    dim3 gGemm2D(8, 16, BATCH);   // Cout=2048
    dim3 gScores(8, 8, BATCH * HEADS);
    dim3 gAttn(8, BATCH * HEADS);

    for (int l = 0; l < LAYERS; l++) {
        transposeS_k<<<gT1, 256>>>(xb, xTh, xTl, DIM, DIM, 0);
        gemmt_k<0><<<gGemmD, 256, GSMEM>>>(Wqh + l * DD, Wql + l * DD, xTh, xTl,
            bq + l * DIM, qb, DIM, DIM, nullptr, nullptr, nullptr, nullptr, nullptr);
        gemmt_k<0><<<gGemmD, 256, GSMEM>>>(Wkh + l * DD, Wkl + l * DD, xTh, xTl,
            bk + l * DIM, kb, DIM, DIM, nullptr, nullptr, nullptr, nullptr, nullptr);
        gemmt_k<0><<<gGemmD, 256, GSMEM>>>(Wvh + l * DD, Wvl + l * DD, xTh, xTl,
            bv + l * DIM, vb2, DIM, DIM, nullptr, nullptr, nullptr, nullptr, nullptr);

        scores_k<<<gScores, 256>>>(qb, kb, sb);
        softmax_k<<<BATCH * HEADS * NSEQ, 256>>>(sb);
        attnv_k<<<gAttn, 256>>>(sb, vb2, ab);

        transposeS_k<<<gT1, 256>>>(ab, aTh, aTl, DIM, DIM, 0);
        gemmt_k<0><<<gGemmD, 256, GSMEM>>>(Wmh + l * DD, Wml + l * DD, aTh, aTl,
            bm + l * DIM, mb, DIM, DIM, nullptr, nullptr, nullptr, nullptr, nullptr);

        // concat-transposed: cT[n, 0:D] = merged^T, cT[n, D:2D] = x^T
        transposeS_k<<<gT1, 256>>>(mb, cTh, cTl, DIM, 2 * DIM, 0);
        transposeS_k<<<gT1, 256>>>(xb, cTh, cTl, DIM, 2 * DIM, DIM);

        gemmt_k<1><<<gGemm2D, 256, GSMEM>>>(Wp1h + l * DD2, Wp1l + l * DD2, cTh, cTl,
            bp1 + l * 2 * DIM, hb, 2 * DIM, 2 * DIM,
            bng + l * 2 * DIM, bnb + l * 2 * DIM,
            bnm + l * 2 * DIM, bnv + l * 2 * DIM, nullptr);

        transposeS_k<<<gT2, 256>>>(hb, hTh, hTl, 2 * DIM, 2 * DIM, 0);

        float* dst = (l == LAYERS - 1) ? (float*)d_out : xb;
        gemmt_k<2><<<gGemmD, 256, GSMEM>>>(Wp2h + l * DD3, Wp2l + l * DD3, hTh, hTl,
            bp2 + l * DIM, dst, DIM, 2 * DIM,
            nullptr, nullptr, nullptr, nullptr, xb);
    }
}

// round 10
// speedup vs baseline: 2.3280x; 1.4556x over previous
#include <cuda_runtime.h>
#include <cuda_bf16.h>
#include <cstdint>
#include <cstddef>

#define NSEQ 1024
#define DIM  1024
#define BATCH 4
#define HEADS 16
#define DK 64
#define LAYERS 4

// ---------------- fp32 scratch ----------------
__device__ float g_x[BATCH * DIM * NSEQ];        // running x  (c,n)
__device__ float g_m[BATCH * DIM * NSEQ];        // merged (c,n)
__device__ float g_h[BATCH * 2 * DIM * NSEQ];    // hidden after BN/ReLU (c,n)

// ---------------- bf16 buffers ----------------
__device__ __align__(256) __nv_bfloat16 g_Wqh[LAYERS * DIM * DIM];
__device__ __align__(256) __nv_bfloat16 g_Wql[LAYERS * DIM * DIM];
__device__ __align__(256) __nv_bfloat16 g_Wkh[LAYERS * DIM * DIM];
__device__ __align__(256) __nv_bfloat16 g_Wkl[LAYERS * DIM * DIM];
__device__ __align__(256) __nv_bfloat16 g_Wvh[LAYERS * DIM * DIM];
__device__ __align__(256) __nv_bfloat16 g_Wvl[LAYERS * DIM * DIM];
__device__ __align__(256) __nv_bfloat16 g_Wmh[LAYERS * DIM * DIM];
__device__ __align__(256) __nv_bfloat16 g_Wml[LAYERS * DIM * DIM];
__device__ __align__(256) __nv_bfloat16 g_Wp1h[LAYERS * 2 * DIM * 2 * DIM];
__device__ __align__(256) __nv_bfloat16 g_Wp1l[LAYERS * 2 * DIM * 2 * DIM];
__device__ __align__(256) __nv_bfloat16 g_Wp2h[LAYERS * DIM * 2 * DIM];
__device__ __align__(256) __nv_bfloat16 g_Wp2l[LAYERS * DIM * 2 * DIM];
__device__ float g_bqP[LAYERS * DIM];
__device__ float g_bkP[LAYERS * DIM];
__device__ float g_bvP[LAYERS * DIM];
__device__ __align__(256) __nv_bfloat16 g_xTh[BATCH * NSEQ * DIM];
__device__ __align__(256) __nv_bfloat16 g_xTl[BATCH * NSEQ * DIM];
__device__ __align__(256) __nv_bfloat16 g_qh[BATCH * DIM * NSEQ];  // [b][h*64+dk][n]
__device__ __align__(256) __nv_bfloat16 g_ql[BATCH * DIM * NSEQ];
__device__ __align__(256) __nv_bfloat16 g_kh[BATCH * DIM * NSEQ];
__device__ __align__(256) __nv_bfloat16 g_kl[BATCH * DIM * NSEQ];
__device__ __align__(256) __nv_bfloat16 g_vh[BATCH * DIM * NSEQ];
__device__ __align__(256) __nv_bfloat16 g_vl[BATCH * DIM * NSEQ];
__device__ __align__(256) __nv_bfloat16 g_aTh[BATCH * NSEQ * DIM];  // flash out [b][n][h*64+dk]
__device__ __align__(256) __nv_bfloat16 g_aTl[BATCH * NSEQ * DIM];
__device__ __align__(256) __nv_bfloat16 g_cTh[BATCH * NSEQ * 2 * DIM];
__device__ __align__(256) __nv_bfloat16 g_cTl[BATCH * NSEQ * 2 * DIM];
__device__ __align__(256) __nv_bfloat16 g_hTh[BATCH * NSEQ * 2 * DIM];
__device__ __align__(256) __nv_bfloat16 g_hTl[BATCH * NSEQ * 2 * DIM];

// ======================= PTX helpers =======================
__device__ __forceinline__ uint32_t smem_u32(const void* p) {
    uint32_t a;
    asm("{ .reg .u64 t; cvta.to.shared.u64 t, %1; cvt.u32.u64 %0, t; }" : "=r"(a) : "l"(p));
    return a;
}
#define CP_ASYNC16(dst, src) \
    asm volatile("cp.async.cg.shared.global [%0], [%1], 16;" :: "r"(dst), "l"(src) : "memory")
#define CP_COMMIT()   asm volatile("cp.async.commit_group;" ::: "memory")
#define CP_WAIT(N)    asm volatile("cp.async.wait_group %0;" :: "n"(N) : "memory")
#define LDM4(r, addr) \
    asm volatile("ldmatrix.sync.aligned.m8n8.x4.shared.b16 {%0,%1,%2,%3}, [%4];" \
        : "=r"((r)[0]), "=r"((r)[1]), "=r"((r)[2]), "=r"((r)[3]) : "r"(addr))
#define LDM4T(r, addr) \
    asm volatile("ldmatrix.sync.aligned.m8n8.x4.trans.shared.b16 {%0,%1,%2,%3}, [%4];" \
        : "=r"((r)[0]), "=r"((r)[1]), "=r"((r)[2]), "=r"((r)[3]) : "r"(addr))
#define MMA_BF16(d, a, b0, b1) \
    asm volatile("mma.sync.aligned.m16n8k16.row.col.f32.bf16.bf16.f32 " \
        "{%0,%1,%2,%3}, {%4,%5,%6,%7}, {%8,%9}, {%0,%1,%2,%3};" \
        : "+f"((d)[0]), "+f"((d)[1]), "+f"((d)[2]), "+f"((d)[3]) \
        : "r"((a)[0]), "r"((a)[1]), "r"((a)[2]), "r"((a)[3]), "r"(b0), "r"(b1))

__device__ __forceinline__ uint32_t packbf(float a, float b) {
    __nv_bfloat16 ha = __float2bfloat16(a), hb = __float2bfloat16(b);
    return (uint32_t)__bfloat16_as_ushort(ha) | ((uint32_t)__bfloat16_as_ushort(hb) << 16);
}

// ======================= tensor GEMM (3x bf16 split, mma.sync) =======================
#define SROW   40
#define MATB   (128 * SROW * 2)
#define STAGEB (4 * MATB)
#define GSMEM  (2 * STAGEB)

template<int EPI>
__global__ __launch_bounds__(256) void gemmt_k(
    const __nv_bfloat16* __restrict__ Wh, const __nv_bfloat16* __restrict__ Wl,
    const __nv_bfloat16* __restrict__ Xh, const __nv_bfloat16* __restrict__ Xl,
    const float* __restrict__ bias, float* __restrict__ out,
    __nv_bfloat16* __restrict__ outH, __nv_bfloat16* __restrict__ outL,
    int Cout, int Cin,
    const float* __restrict__ g, const float* __restrict__ bt,
    const float* __restrict__ mu, const float* __restrict__ var,
    const float* __restrict__ res)
{
    extern __shared__ __align__(16) char sm[];
    const int tid = threadIdx.x;
    const int l = tid & 31, wid = tid >> 5;
    const int wm = wid & 1, wn = wid >> 1;
    const int b = blockIdx.z, n0 = blockIdx.x * 128, o0 = blockIdx.y * 128;

    const __nv_bfloat16* WhB = Wh + (size_t)o0 * Cin;
    const __nv_bfloat16* WlB = Wl + (size_t)o0 * Cin;
    const __nv_bfloat16* XhB = Xh + ((size_t)b * NSEQ + n0) * Cin;
    const __nv_bfloat16* XlB = Xl + ((size_t)b * NSEQ + n0) * Cin;

    const uint32_t sbase = smem_u32(sm);
    const int NC = Cin >> 5;

    const int rowA = l & 15;
    const int colA = (l >> 4) << 3;
    int aoff[4];
    #pragma unroll
    for (int mt = 0; mt < 4; mt++)
        aoff[mt] = ((wm * 64 + mt * 16 + rowA) * SROW + colA) * 2;
    int boff[2];
    #pragma unroll
    for (int ntp = 0; ntp < 2; ntp++)
        boff[ntp] = ((wn * 32 + ntp * 16 + ((l >> 4) & 1) * 8 + (l & 7)) * SROW
                     + ((l >> 3) & 1) * 8) * 2;

    float acc[4][4][4];
    #pragma unroll
    for (int i = 0; i < 4; i++)
        #pragma unroll
        for (int j = 0; j < 4; j++)
            #pragma unroll
            for (int q = 0; q < 4; q++) acc[i][j][q] = 0.f;

    auto load = [&](int kc) {
        char* base = sm + (kc & 1) * STAGEB;
        const __nv_bfloat16* srcs[4] = {WhB, WlB, XhB, XlB};
        #pragma unroll
        for (int i = 0; i < 2; i++) {
            int s = tid * 2 + i;
            int row = s >> 2, seg = s & 3;
            #pragma unroll
            for (int m4 = 0; m4 < 4; m4++) {
                uint32_t dst = smem_u32(base + m4 * MATB + row * (SROW * 2) + seg * 16);
                const __nv_bfloat16* src = srcs[m4] + (size_t)row * Cin + kc * 32 + seg * 8;
                CP_ASYNC16(dst, src);
            }
        }
        CP_COMMIT();
    };

    load(0);
    for (int kc = 0; kc < NC; kc++) {
        if (kc + 1 < NC) { load(kc + 1); CP_WAIT(1); }
        else            { CP_WAIT(0); }
        __syncthreads();

        const uint32_t S = sbase + (kc & 1) * STAGEB;
        #pragma unroll
        for (int ks = 0; ks < 2; ks++) {
            unsigned fa[4][4], fbh[2][4], fbl[2][4];
            #pragma unroll
            for (int mt = 0; mt < 4; mt++) LDM4(fa[mt], S + aoff[mt] + ks * 32);
            #pragma unroll
            for (int p = 0; p < 2; p++) {
                LDM4(fbh[p], S + 2 * MATB + boff[p] + ks * 32);
                LDM4(fbl[p], S + 3 * MATB + boff[p] + ks * 32);
            }
            #pragma unroll
            for (int mt = 0; mt < 4; mt++)
                #pragma unroll
                for (int nt = 0; nt < 4; nt++) {
                    MMA_BF16(acc[mt][nt], fa[mt], fbh[nt >> 1][(nt & 1) * 2],
                             fbh[nt >> 1][(nt & 1) * 2 + 1]);
                    MMA_BF16(acc[mt][nt], fa[mt], fbl[nt >> 1][(nt & 1) * 2],
                             fbl[nt >> 1][(nt & 1) * 2 + 1]);
                }
            #pragma unroll
            for (int mt = 0; mt < 4; mt++) LDM4(fa[mt], S + MATB + aoff[mt] + ks * 32);
            #pragma unroll
            for (int mt = 0; mt < 4; mt++)
                #pragma unroll
                for (int nt = 0; nt < 4; nt++)
                    MMA_BF16(acc[mt][nt], fa[mt], fbh[nt >> 1][(nt & 1) * 2],
                             fbh[nt >> 1][(nt & 1) * 2 + 1]);
        }
        __syncthreads();
    }

    // ---------------- epilogue ----------------
    #pragma unroll
    for (int mt = 0; mt < 4; mt++) {
        int o1 = o0 + wm * 64 + mt * 16 + (l >> 2);
        int o2 = o1 + 8;
        float b1v = bias[o1], b2v = bias[o2];
        float sc1 = 1.f, sh1 = 0.f, sc2 = 1.f, sh2 = 0.f;
        if (EPI == 1) {
            float s1 = g[o1] * rsqrtf(var[o1] + 1e-5f);
            sc1 = s1; sh1 = bt[o1] - mu[o1] * s1;
            float s2 = g[o2] * rsqrtf(var[o2] + 1e-5f);
            sc2 = s2; sh2 = bt[o2] - mu[o2] * s2;
        }
        size_t r1i = ((size_t)b * Cout + o1) * NSEQ + n0 + wn * 32;
        size_t r2i = ((size_t)b * Cout + o2) * NSEQ + n0 + wn * 32;
        #pragma unroll
        for (int nt = 0; nt < 4; nt++) {
            int nn = nt * 8 + (l & 3) * 2;
            float v0 = acc[mt][nt][0] + b1v, v1 = acc[mt][nt][1] + b1v;
            float v2 = acc[mt][nt][2] + b2v, v3 = acc[mt][nt][3] + b2v;
            if (EPI == 1) {
                v0 = fmaxf(fmaf(v0, sc1, sh1), 0.f); v1 = fmaxf(fmaf(v1, sc1, sh1), 0.f);
                v2 = fmaxf(fmaf(v2, sc2, sh2), 0.f); v3 = fmaxf(fmaf(v3, sc2, sh2), 0.f);
            }
            if (EPI == 2) {
                float2 ra = *(const float2*)(res + r1i + nn);
                float2 rb = *(const float2*)(res + r2i + nn);
                v0 += ra.x; v1 += ra.y; v2 += rb.x; v3 += rb.y;
            }
            if (EPI == 3) {
                __nv_bfloat16 h0 = __float2bfloat16(v0), h1 = __float2bfloat16(v1);
                __nv_bfloat16 h2 = __float2bfloat16(v2), h3 = __float2bfloat16(v3);
                uint32_t H1 = (uint32_t)__bfloat16_as_ushort(h0) | ((uint32_t)__bfloat16_as_ushort(h1) << 16);
                uint32_t H2 = (uint32_t)__bfloat16_as_ushort(h2) | ((uint32_t)__bfloat16_as_ushort(h3) << 16);
                uint32_t L1 = packbf(v0 - __bfloat162float(h0), v1 - __bfloat162float(h1));
                uint32_t L2 = packbf(v2 - __bfloat162float(h2), v3 - __bfloat162float(h3));
                *(uint32_t*)(outH + r1i + nn) = H1;
                *(uint32_t*)(outH + r2i + nn) = H2;
                *(uint32_t*)(outL + r1i + nn) = L1;
                *(uint32_t*)(outL + r2i + nn) = L2;
            } else {
                *(float2*)(out + r1i + nn) = make_float2(v0, v1);
                *(float2*)(out + r2i + nn) = make_float2(v2, v3);
            }
        }
    }
}

// ======================= flash attention (mma.sync, 3x split) =======================
// Q,K,V: bf16 hi/lo, layout [b][h*64+dk][n]  (per head: [dk][n]/[dk][m])
// Output: [b][n][h*64+dk] bf16 hi/lo (transposed-split, ready for merged GEMM)
#define FSROW 136
#define FROWB (FSROW * 2)        // 272 B
#define FMATB (64 * FROWB)       // 17408 B
#define FSMEM (10 * FMATB)       // 174080 B

__global__ __launch_bounds__(256, 1) void flash_k(
    const __nv_bfloat16* __restrict__ Qh, const __nv_bfloat16* __restrict__ Ql,
    const __nv_bfloat16* __restrict__ Kh, const __nv_bfloat16* __restrict__ Kl,
    const __nv_bfloat16* __restrict__ Vh, const __nv_bfloat16* __restrict__ Vl,
    __nv_bfloat16* __restrict__ Oh, __nv_bfloat16* __restrict__ Ol)
{
    extern __shared__ __align__(16) char sm[];
    const int tid = threadIdx.x, l = tid & 31, w = tid >> 5;
    const int n0 = blockIdx.x * 128;
    const int bh = blockIdx.y;
    const int b = bh >> 4, h = bh & 15;
    const size_t hbase = ((size_t)b * DIM + h * 64) * NSEQ;
    const uint32_t sb = smem_u32(sm);

    // ---- q load (matrices 0,1 = qh,ql) ----
    {
        const __nv_bfloat16* srcs[2] = {Qh + hbase + n0, Ql + hbase + n0};
        #pragma unroll
        for (int m4 = 0; m4 < 2; m4++)
            #pragma unroll
            for (int i = 0; i < 4; i++) {
                int idx = tid + i * 256;
                int row = idx >> 4, seg = idx & 15;
                CP_ASYNC16(sb + m4 * FMATB + row * FROWB + seg * 16,
                           (const char*)(srcs[m4] + (size_t)row * NSEQ) + seg * 16);
            }
    }
    auto load_kv = [&](int kc) {
        int m0 = kc * 128;
        const __nv_bfloat16* srcs[4] = {Kh + hbase + m0, Kl + hbase + m0,
                                        Vh + hbase + m0, Vl + hbase + m0};
        uint32_t stg = sb + 2 * FMATB + (kc & 1) * 4 * FMATB;
        #pragma unroll
        for (int m4 = 0; m4 < 4; m4++)
            #pragma unroll
            for (int i = 0; i < 4; i++) {
                int idx = tid + i * 256;
                int row = idx >> 4, seg = idx & 15;
                CP_ASYNC16(stg + m4 * FMATB + row * FROWB + seg * 16,
                           (const char*)(srcs[m4] + (size_t)row * NSEQ) + seg * 16);
            }
    };
    load_kv(0); CP_COMMIT();
    load_kv(1); CP_COMMIT();
    CP_WAIT(1); __syncthreads();

    // ---- preload Q a-frags (trans ldmatrix from [dk][n]) ----
    unsigned qfh[4][4], qfl[4][4];
    {
        int row_in = ((l >> 4) & 1) * 8 + (l & 7);
        int col = w * 16 + ((l >> 3) & 1) * 8;
        #pragma unroll
        for (int ks = 0; ks < 4; ks++) {
            uint32_t a = sb + (ks * 16 + row_in) * FROWB + col * 2;
            LDM4T(qfh[ks], a);
            LDM4T(qfl[ks], a + FMATB);
        }
    }

    float Oacc[8][4];
    #pragma unroll
    for (int u = 0; u < 8; u++)
        #pragma unroll
        for (int q = 0; q < 4; q++) Oacc[u][q] = 0.f;
    float rm0 = -1e30f, rm1 = -1e30f, rs0 = 0.f, rs1 = 0.f;

    const int krow = ((l >> 3) & 1) * 8 + (l & 7);
    const int kcol = ((l >> 4) & 1) * 8;
    const int vrow = ((l >> 4) & 1) * 8 + (l & 7);
    const int vcol = ((l >> 3) & 1) * 8;

    for (int kc = 0; kc < 8; kc++) {
        uint32_t stg = sb + 2 * FMATB + (kc & 1) * 4 * FMATB;

        // ---- S = Q K^T (3 passes) ----
        float sacc[16][4];
        #pragma unroll
        for (int t = 0; t < 16; t++)
            #pragma unroll
            for (int q = 0; q < 4; q++) sacc[t][q] = 0.f;

        #pragma unroll
        for (int j = 0; j < 8; j++) {
            #pragma unroll
            for (int ks = 0; ks < 4; ks++) {
                unsigned bh4[4], bl4[4];
                uint32_t a = stg + (ks * 16 + krow) * FROWB + (j * 16 + kcol) * 2;
                LDM4T(bh4, a);
                LDM4T(bl4, a + FMATB);
                MMA_BF16(sacc[2 * j],     qfh[ks], bh4[0], bh4[1]);
                MMA_BF16(sacc[2 * j + 1], qfh[ks], bh4[2], bh4[3]);
                MMA_BF16(sacc[2 * j],     qfh[ks], bl4[0], bl4[1]);
                MMA_BF16(sacc[2 * j + 1], qfh[ks], bl4[2], bl4[3]);
                MMA_BF16(sacc[2 * j],     qfl[ks], bh4[0], bh4[1]);
                MMA_BF16(sacc[2 * j + 1], qfl[ks], bh4[2], bh4[3]);
            }
        }

        // ---- online softmax ----
        float cm0 = -1e30f, cm1 = -1e30f;
        #pragma unroll
        for (int t = 0; t < 16; t++) {
            sacc[t][0] *= 0.125f; sacc[t][1] *= 0.125f;
            sacc[t][2] *= 0.125f; sacc[t][3] *= 0.125f;
            cm0 = fmaxf(cm0, fmaxf(sacc[t][0], sacc[t][1]));
            cm1 = fmaxf(cm1, fmaxf(sacc[t][2], sacc[t][3]));
        }
        cm0 = fmaxf(cm0, __shfl_xor_sync(0xffffffffu, cm0, 1));
        cm0 = fmaxf(cm0, __shfl_xor_sync(0xffffffffu, cm0, 2));
        cm1 = fmaxf(cm1, __shfl_xor_sync(0xffffffffu, cm1, 1));
        cm1 = fmaxf(cm1, __shfl_xor_sync(0xffffffffu, cm1, 2));
        float nm0 = fmaxf(rm0, cm0), nm1 = fmaxf(rm1, cm1);
        float al0 = __expf(rm0 - nm0), al1 = __expf(rm1 - nm1);
        rm0 = nm0; rm1 = nm1;

        float cs0 = 0.f, cs1 = 0.f;
        #pragma unroll
        for (int t = 0; t < 16; t++) {
            sacc[t][0] = __expf(sacc[t][0] - nm0);
            sacc[t][1] = __expf(sacc[t][1] - nm0);
            sacc[t][2] = __expf(sacc[t][2] - nm1);
            sacc[t][3] = __expf(sacc[t][3] - nm1);
            cs0 += sacc[t][0] + sacc[t][1];
            cs1 += sacc[t][2] + sacc[t][3];
        }
        cs0 += __shfl_xor_sync(0xffffffffu, cs0, 1);
        cs0 += __shfl_xor_sync(0xffffffffu, cs0, 2);
        cs1 += __shfl_xor_sync(0xffffffffu, cs1, 1);
        cs1 += __shfl_xor_sync(0xffffffffu, cs1, 2);
        rs0 = rs0 * al0 + cs0;
        rs1 = rs1 * al1 + cs1;
        #pragma unroll
        for (int u = 0; u < 8; u++) {
            Oacc[u][0] *= al0; Oacc[u][1] *= al0;
            Oacc[u][2] *= al1; Oacc[u][3] *= al1;
        }

        // ---- O += P V ----
        #pragma unroll
        for (int kk = 0; kk < 8; kk++) {
            unsigned pfh[4], pfl[4];
            {
                float p0 = sacc[2 * kk][0],     p1 = sacc[2 * kk][1];
                float p2 = sacc[2 * kk][2],     p3 = sacc[2 * kk][3];
                float p4 = sacc[2 * kk + 1][0], p5 = sacc[2 * kk + 1][1];
                float p6 = sacc[2 * kk + 1][2], p7 = sacc[2 * kk + 1][3];
                __nv_bfloat16 h0 = __float2bfloat16(p0), h1 = __float2bfloat16(p1);
                __nv_bfloat16 h2 = __float2bfloat16(p2), h3 = __float2bfloat16(p3);
                __nv_bfloat16 h4 = __float2bfloat16(p4), h5 = __float2bfloat16(p5);
                __nv_bfloat16 h6 = __float2bfloat16(p6), h7 = __float2bfloat16(p7);
                pfh[0] = (uint32_t)__bfloat16_as_ushort(h0) | ((uint32_t)__bfloat16_as_ushort(h1) << 16);
                pfh[1] = (uint32_t)__bfloat16_as_ushort(h2) | ((uint32_t)__bfloat16_as_ushort(h3) << 16);
                pfh[2] = (uint32_t)__bfloat16_as_ushort(h4) | ((uint32_t)__bfloat16_as_ushort(h5) << 16);
                pfh[3] = (uint32_t)__bfloat16_as_ushort(h6) | ((uint32_t)__bfloat16_as_ushort(h7) << 16);
                pfl[0] = packbf(p0 - __bfloat162float(h0), p1 - __bfloat162float(h1));
                pfl[1] = packbf(p2 - __bfloat162float(h2), p3 - __bfloat162float(h3));
                pfl[2] = packbf(p4 - __bfloat162float(h4), p5 - __bfloat162float(h5));
                pfl[3] = packbf(p6 - __bfloat162float(h6), p7 - __bfloat162float(h7));
            }
            #pragma unroll
            for (int t = 0; t < 4; t++) {
                unsigned vh4[4], vl4[4];
                uint32_t a = stg + 2 * FMATB + (t * 16 + vrow) * FROWB + (kk * 16 + vcol) * 2;
                LDM4(vh4, a);
                LDM4(vl4, a + FMATB);
                MMA_BF16(Oacc[2 * t],     pfh, vh4[0], vh4[1]);
                MMA_BF16(Oacc[2 * t + 1], pfh, vh4[2], vh4[3]);
                MMA_BF16(Oacc[2 * t],     pfl, vh4[0], vh4[1]);
                MMA_BF16(Oacc[2 * t + 1], pfl, vh4[2], vh4[3]);
                MMA_BF16(Oacc[2 * t],     pfh, vl4[0], vl4[1]);
                MMA_BF16(Oacc[2 * t + 1], pfh, vl4[2], vl4[3]);
            }
        }
        __syncthreads();
        if (kc + 2 < 8) {
            load_kv(kc + 2); CP_COMMIT();
            CP_WAIT(1); __syncthreads();
        } else if (kc + 1 < 8) {
            // no more loads in flight to hide behind: drain everything
            CP_WAIT(0); __syncthreads();
        }
    }

    // ---- finalize ----
    float inv0 = 1.f / rs0, inv1 = 1.f / rs1;
    int nr0 = n0 + w * 16 + (l >> 2);
    int nr1 = nr0 + 8;
    size_t base0 = ((size_t)b * NSEQ + nr0) * DIM + h * 64;
    size_t base1 = ((size_t)b * NSEQ + nr1) * DIM + h * 64;
    #pragma unroll
    for (int u = 0; u < 8; u++) {
        int dk = u * 8 + 2 * (l & 3);
        float v0 = Oacc[u][0] * inv0, v1 = Oacc[u][1] * inv0;
        float v2 = Oacc[u][2] * inv1, v3 = Oacc[u][3] * inv1;
        __nv_bfloat16 h0 = __float2bfloat16(v0), h1 = __float2bfloat16(v1);
        __nv_bfloat16 h2 = __float2bfloat16(v2), h3 = __float2bfloat16(v3);
        *(uint32_t*)(Oh + base0 + dk) =
            (uint32_t)__bfloat16_as_ushort(h0) | ((uint32_t)__bfloat16_as_ushort(h1) << 16);
        *(uint32_t*)(Oh + base1 + dk) =
            (uint32_t)__bfloat16_as_ushort(h2) | ((uint32_t)__bfloat16_as_ushort(h3) << 16);
        *(uint32_t*)(Ol + base0 + dk) = packbf(v0 - __bfloat162float(h0), v1 - __bfloat162float(h1));
        *(uint32_t*)(Ol + base1 + dk) = packbf(v2 - __bfloat162float(h2), v3 - __bfloat162float(h3));
    }
}

// ======================= weight split kernels =======================
__global__ __launch_bounds__(256) void split_k(
    const float* __restrict__ src, __nv_bfloat16* __restrict__ hi,
    __nv_bfloat16* __restrict__ lo, int n4)
{
    int i = blockIdx.x * 256 + threadIdx.x;
    if (i >= n4) return;
    float4 v = ((const float4*)src)[i];
    __nv_bfloat16 hx = __float2bfloat16(v.x), hy = __float2bfloat16(v.y);
    __nv_bfloat16 hz = __float2bfloat16(v.z), hw = __float2bfloat16(v.w);
    uint2 H, L;
    H.x = (uint32_t)__bfloat16_as_ushort(hx) | ((uint32_t)__bfloat16_as_ushort(hy) << 16);
    H.y = (uint32_t)__bfloat16_as_ushort(hz) | ((uint32_t)__bfloat16_as_ushort(hw) << 16);
    L.x = packbf(v.x - __bfloat162float(hx), v.y - __bfloat162float(hy));
    L.y = packbf(v.z - __bfloat162float(hz), v.w - __bfloat162float(hw));
    ((uint2*)hi)[i] = H;
    ((uint2*)lo)[i] = L;
}

// row-permuted split: out[layer, o'=h*64+dk, c] = in[layer, dk*16+h, c]
__global__ __launch_bounds__(256) void split_permR_k(
    const float* __restrict__ src, __nv_bfloat16* __restrict__ hi,
    __nv_bfloat16* __restrict__ lo)
{
    int i = blockIdx.x * 256 + threadIdx.x;
    int row = i / (DIM / 4), c4 = i % (DIM / 4);
    int layer = row / DIM, op = row % DIM;
    int o = ((op & 63) << 4) + (op >> 6);
    float4 v = ((const float4*)src)[((size_t)layer * DIM + o) * (DIM / 4) + c4];
    __nv_bfloat16 hx = __float2bfloat16(v.x), hy = __float2bfloat16(v.y);
    __nv_bfloat16 hz = __float2bfloat16(v.z), hw = __float2bfloat16(v.w);
    uint2 H, L;
    H.x = (uint32_t)__bfloat16_as_ushort(hx) | ((uint32_t)__bfloat16_as_ushort(hy) << 16);
    H.y = (uint32_t)__bfloat16_as_ushort(hz) | ((uint32_t)__bfloat16_as_ushort(hw) << 16);
    L.x = packbf(v.x - __bfloat162float(hx), v.y - __bfloat162float(hy));
    L.y = packbf(v.z - __bfloat162float(hz), v.w - __bfloat162float(hw));
    ((uint2*)hi)[i] = H;
    ((uint2*)lo)[i] = L;
}

// col-permuted split: out[layer, o, c'=h*64+dk] = in[layer, o, dk*16+h]
__global__ __launch_bounds__(256) void split_permC_k(
    const float* __restrict__ src, __nv_bfloat16* __restrict__ hi,
    __nv_bfloat16* __restrict__ lo)
{
    int i = blockIdx.x * 256 + threadIdx.x;
    int row = i / DIM, cp = i % DIM;
    int c = ((cp & 63) << 4) + (cp >> 6);
    float v = src[(size_t)row * DIM + c];
    __nv_bfloat16 hv = __float2bfloat16(v);
    hi[i] = hv;
    lo[i] = __float2bfloat16(v - __bfloat162float(hv));
}

__global__ __launch_bounds__(256) void permB_k(
    const float* __restrict__ src, float* __restrict__ dst)
{
    int i = blockIdx.x * 256 + threadIdx.x;
    int layer = i / DIM, op = i % DIM;
    dst[i] = src[layer * DIM + ((op & 63) << 4) + (op >> 6)];
}

// ======================= transpose + split =======================
__global__ __launch_bounds__(256) void transposeS_k(
    const float* __restrict__ src, __nv_bfloat16* __restrict__ dstH,
    __nv_bfloat16* __restrict__ dstL, int C, int dstStride, int dstOff)
{
    __shared__ float t[32][33];
    const int b  = blockIdx.z;
    const int n0 = blockIdx.x * 32;
    const int c0 = blockIdx.y * 32;
    const float* s = src + (size_t)b * C * NSEQ;
    const size_t dbase = (size_t)b * NSEQ * dstStride + dstOff;
    const int tx = threadIdx.x & 31, ty = threadIdx.x >> 5;
    #pragma unroll
    for (int i = 0; i < 32; i += 8)
        t[ty + i][tx] = s[(size_t)(c0 + ty + i) * NSEQ + n0 + tx];
    __syncthreads();
    #pragma unroll
    for (int i = 0; i < 32; i += 8) {
        float v = t[tx][ty + i];
        __nv_bfloat16 hv = __float2bfloat16(v);
        size_t idx = dbase + (size_t)(n0 + ty + i) * dstStride + c0 + tx;
        dstH[idx] = hv;
        dstL[idx] = __float2bfloat16(v - __bfloat162float(hv));
    }
}

// ======================= host launcher =======================
extern "C" void kernel_launch(void* const* d_in, const int* in_sizes, int n_in,
                              void* d_out, int out_size)
{
    const float* motion = (const float*)d_in[0];
    const float* Wq  = (const float*)d_in[1];
    const float* bq  = (const float*)d_in[2];
    const float* Wk  = (const float*)d_in[3];
    const float* bk  = (const float*)d_in[4];
    const float* Wv  = (const float*)d_in[5];
    const float* bv  = (const float*)d_in[6];
    const float* Wm  = (const float*)d_in[7];
    const float* bm  = (const float*)d_in[8];
    const float* Wp1 = (const float*)d_in[9];
    const float* bp1 = (const float*)d_in[10];
    const float* bng = (const float*)d_in[11];
    const float* bnb = (const float*)d_in[12];
    const float* bnm = (const float*)d_in[13];
    const float* bnv = (const float*)d_in[14];
    const float* Wp2 = (const float*)d_in[15];
    const float* bp2 = (const float*)d_in[16];

    float *xb, *mb, *hb, *bqP, *bkP, *bvP;
    cudaGetSymbolAddress((void**)&xb, g_x);
    cudaGetSymbolAddress((void**)&mb, g_m);
    cudaGetSymbolAddress((void**)&hb, g_h);
    cudaGetSymbolAddress((void**)&bqP, g_bqP);
    cudaGetSymbolAddress((void**)&bkP, g_bkP);
    cudaGetSymbolAddress((void**)&bvP, g_bvP);

    __nv_bfloat16 *Wqh, *Wql, *Wkh, *Wkl, *Wvh, *Wvl, *Wmh, *Wml;
    __nv_bfloat16 *Wp1h, *Wp1l, *Wp2h, *Wp2l;
    __nv_bfloat16 *xTh, *xTl, *aTh, *aTl, *cTh, *cTl, *hTh, *hTl;
    __nv_bfloat16 *qh, *ql, *kh, *kl, *vh, *vl;
    cudaGetSymbolAddress((void**)&Wqh, g_Wqh);  cudaGetSymbolAddress((void**)&Wql, g_Wql);
    cudaGetSymbolAddress((void**)&Wkh, g_Wkh);  cudaGetSymbolAddress((void**)&Wkl, g_Wkl);
    cudaGetSymbolAddress((void**)&Wvh, g_Wvh);  cudaGetSymbolAddress((void**)&Wvl, g_Wvl);
    cudaGetSymbolAddress((void**)&Wmh, g_Wmh);  cudaGetSymbolAddress((void**)&Wml, g_Wml);
    cudaGetSymbolAddress((void**)&Wp1h, g_Wp1h); cudaGetSymbolAddress((void**)&Wp1l, g_Wp1l);
    cudaGetSymbolAddress((void**)&Wp2h, g_Wp2h); cudaGetSymbolAddress((void**)&Wp2l, g_Wp2l);
    cudaGetSymbolAddress((void**)&xTh, g_xTh);  cudaGetSymbolAddress((void**)&xTl, g_xTl);
    cudaGetSymbolAddress((void**)&aTh, g_aTh);  cudaGetSymbolAddress((void**)&aTl, g_aTl);
    cudaGetSymbolAddress((void**)&cTh, g_cTh);  cudaGetSymbolAddress((void**)&cTl, g_cTl);
    cudaGetSymbolAddress((void**)&hTh, g_hTh);  cudaGetSymbolAddress((void**)&hTl, g_hTl);
    cudaGetSymbolAddress((void**)&qh, g_qh);    cudaGetSymbolAddress((void**)&ql, g_ql);
    cudaGetSymbolAddress((void**)&kh, g_kh);    cudaGetSymbolAddress((void**)&kl, g_kl);
    cudaGetSymbolAddress((void**)&vh, g_vh);    cudaGetSymbolAddress((void**)&vl, g_vl);

    cudaFuncSetAttribute(gemmt_k<0>, cudaFuncAttributeMaxDynamicSharedMemorySize, GSMEM);
    cudaFuncSetAttribute(gemmt_k<1>, cudaFuncAttributeMaxDynamicSharedMemorySize, GSMEM);
    cudaFuncSetAttribute(gemmt_k<2>, cudaFuncAttributeMaxDynamicSharedMemorySize, GSMEM);
    cudaFuncSetAttribute(gemmt_k<3>, cudaFuncAttributeMaxDynamicSharedMemorySize, GSMEM);
    cudaFuncSetAttribute(flash_k, cudaFuncAttributeMaxDynamicSharedMemorySize, FSMEM);

    cudaMemcpyAsync(xb, motion, (size_t)BATCH * DIM * NSEQ * sizeof(float),
                    cudaMemcpyDeviceToDevice);

    // ---- weight prep ----
    const int nW  = LAYERS * DIM * DIM;
    const int nP1 = LAYERS * 2 * DIM * 2 * DIM;
    const int nP2 = LAYERS * DIM * 2 * DIM;
    split_permR_k<<<nW / 4 / 256, 256>>>(Wq, Wqh, Wql);
    split_permR_k<<<nW / 4 / 256, 256>>>(Wk, Wkh, Wkl);
    split_permR_k<<<nW / 4 / 256, 256>>>(Wv, Wvh, Wvl);
    split_permC_k<<<nW / 256, 256>>>(Wm, Wmh, Wml);
    split_k<<<(nP1 / 4 + 255) / 256, 256>>>(Wp1, Wp1h, Wp1l, nP1 / 4);
    split_k<<<(nP2 / 4 + 255) / 256, 256>>>(Wp2, Wp2h, Wp2l, nP2 / 4);
    permB_k<<<LAYERS * DIM / 256, 256>>>(bq, bqP);
    permB_k<<<LAYERS * DIM / 256, 256>>>(bk, bkP);
    permB_k<<<LAYERS * DIM / 256, 256>>>(bv, bvP);

    const size_t DD  = (size_t)DIM * DIM;
    const size_t DD2 = (size_t)2 * DIM * 2 * DIM;
    const size_t DD3 = (size_t)DIM * 2 * DIM;

    dim3 gT1(NSEQ / 32, DIM / 32, BATCH);
    dim3 gT2(NSEQ / 32, 2 * DIM / 32, BATCH);
    dim3 gGemmD(8, 8, BATCH);
    dim3 gGemm2D(8, 16, BATCH);
    dim3 gFlash(NSEQ / 128, BATCH * HEADS);

    for (int l = 0; l < LAYERS; l++) {
        transposeS_k<<<gT1, 256>>>(xb, xTh, xTl, DIM, DIM, 0);
        gemmt_k<3><<<gGemmD, 256, GSMEM>>>(Wqh + l * DD, Wql + l * DD, xTh, xTl,
            bqP + l * DIM, nullptr, qh, ql, DIM, DIM,
            nullptr, nullptr, nullptr, nullptr, nullptr);
        gemmt_k<3><<<gGemmD, 256, GSMEM>>>(Wkh + l * DD, Wkl + l * DD, xTh, xTl,
            bkP + l * DIM, nullptr, kh, kl, DIM, DIM,
            nullptr, nullptr, nullptr, nullptr, nullptr);
        gemmt_k<3><<<gGemmD, 256, GSMEM>>>(Wvh + l * DD, Wvl + l * DD, xTh, xTl,
            bvP + l * DIM, nullptr, vh, vl, DIM, DIM,
            nullptr, nullptr, nullptr, nullptr, nullptr);

        flash_k<<<gFlash, 256, FSMEM>>>(qh, ql, kh, kl, vh, vl, aTh, aTl);

        gemmt_k<0><<<gGemmD, 256, GSMEM>>>(Wmh + l * DD, Wml + l * DD, aTh, aTl,
            bm + l * DIM, mb, nullptr, nullptr, DIM, DIM,
            nullptr, nullptr, nullptr, nullptr, nullptr);

        transposeS_k<<<gT1, 256>>>(mb, cTh, cTl, DIM, 2 * DIM, 0);
        transposeS_k<<<gT1, 256>>>(xb, cTh, cTl, DIM, 2 * DIM, DIM);

        gemmt_k<1><<<gGemm2D, 256, GSMEM>>>(Wp1h + l * DD2, Wp1l + l * DD2, cTh, cTl,
            bp1 + l * 2 * DIM, hb, nullptr, nullptr, 2 * DIM, 2 * DIM,
            bng + l * 2 * DIM, bnb + l * 2 * DIM,
            bnm + l * 2 * DIM, bnv + l * 2 * DIM, nullptr);

        transposeS_k<<<gT2, 256>>>(hb, hTh, hTl, 2 * DIM, 2 * DIM, 0);

        float* dst = (l == LAYERS - 1) ? (float*)d_out : xb;
        gemmt_k<2><<<gGemmD, 256, GSMEM>>>(Wp2h + l * DD3, Wp2l + l * DD3, hTh, hTl,
            bp2 + l * DIM, dst, nullptr, nullptr, DIM, 2 * DIM,
            nullptr, nullptr, nullptr, nullptr, xb);
    }
}